// round 6
// baseline (speedup 1.0000x reference)
#include <cuda_runtime.h>

#define N_      4
#define H_      64
#define W_      64
#define INC_    256
#define CM_     64
#define OUTC_   256
#define HW_     (H_ * W_)       // 4096
#define HO_     (2 * H_)        // 128
#define NCHUNK_ 4               // ic chunks for enc conv (16 ic each)
#define MF_     (CM_ + OUTC_)   // 320 fused output channels

// ---------------- scratch (device globals; no allocation allowed) ----------
__device__ float g_t1[N_ * CM_ * HW_];              // down-conv output   (4 MB)
__device__ float g_y [N_ * OUTC_ * HW_];            // out-conv on lowres (16 MB)
__device__ float g_kern[N_ * 100 * HW_];            // softmax kernels, channel-major
__device__ float g_part[NCHUNK_ * N_ * 100 * HW_];  // enc conv partials  (26 MB)
__device__ float g_wt[CM_ * 9 * 112];               // transposed enc weights
__device__ float g_wtc[INC_ * MF_];                 // fused W transposed [k][m: 64 down | 256 out]

__device__ __forceinline__ unsigned long long fma2(unsigned long long a,
                                                   unsigned long long b,
                                                   unsigned long long c) {
    unsigned long long d;
    asm("fma.rn.f32x2 %0, %1, %2, %3;" : "=l"(d) : "l"(a), "l"(b), "l"(c));
    return d;
}
__device__ __forceinline__ unsigned long long pack2(float x) {
    unsigned long long r;
    asm("mov.b64 %0, {%1, %1};" : "=l"(r) : "f"(x));
    return r;
}
__device__ __forceinline__ float2 unpack2(unsigned long long a) {
    float2 r;
    asm("mov.b64 {%0, %1}, %2;" : "=f"(r.x), "=f"(r.y) : "l"(a));
    return r;
}

// ---------------- K0: all weight transposes ---------------------------------
// [0, 64512): enc weights -> g_wt [ic][tap][d][k pad 28]
// [64512, 146432): fused conv weights -> g_wtc [k][m]
__global__ void wt_kernel(const float* __restrict__ w_enc,
                          const float* __restrict__ w_out,
                          const float* __restrict__ w_down) {
    int idx = blockIdx.x * 256 + threadIdx.x;
    if (idx < 64512) {
        int ic  = idx / (9 * 112);
        int r   = idx % (9 * 112);
        int t   = r / 112;
        int dk  = r % 112;
        int d   = dk / 28;
        int k   = dk % 28;
        float v = 0.f;
        if (k < 25) v = w_enc[((k * 4 + d) * CM_ + ic) * 9 + t];
        g_wt[idx] = v;
    } else if (idx < 64512 + INC_ * MF_) {
        int j = idx - 64512;
        int k = j / MF_, m = j % MF_;
        g_wtc[j] = (m < CM_) ? w_down[m * INC_ + k]
                             : w_out[(m - CM_) * INC_ + k];
    }
}

// ---------------- K1+K3 fused: 1x1 convs as one tiled SGEMM (f32x2) --------
// m0 = blockIdx.x*64; block 0 -> g_t1 (down, +bias), blocks 1..4 -> g_y (out)
__global__ void __launch_bounds__(256) convfused_kernel(
        const float* __restrict__ X, const float* __restrict__ bDown) {
    __shared__ __align__(16) float As[32][64];   // [k][m]
    __shared__ __align__(16) float Bs[32][64];   // [k][p]

    int n  = blockIdx.z;
    int m0 = blockIdx.x * 64;
    int p0 = blockIdx.y * 64;
    int tid = threadIdx.x;
    int tr = tid >> 4;
    int tc = tid & 15;

    const float* Xn = X + (size_t)n * INC_ * HW_;

    float4 pa[2], pb[2];
#pragma unroll
    for (int it = 0; it < 2; it++) {
        int i = tid + it * 256;
        int rr = i >> 4, cc = i & 15;
        pa[it] = *(const float4*)(g_wtc + (size_t)rr * MF_ + m0 + cc * 4);
        pb[it] = *(const float4*)(Xn + (size_t)rr * HW_ + p0 + cc * 4);
    }

    unsigned long long acc[4][2];
#pragma unroll
    for (int i = 0; i < 4; i++) { acc[i][0] = 0ull; acc[i][1] = 0ull; }

    for (int k0 = 0; k0 < INC_; k0 += 32) {
        __syncthreads();
#pragma unroll
        for (int it = 0; it < 2; it++) {
            int i = tid + it * 256;
            int rr = i >> 4, cc = i & 15;
            *(float4*)&As[rr][cc * 4] = pa[it];
            *(float4*)&Bs[rr][cc * 4] = pb[it];
        }
        __syncthreads();
        if (k0 + 32 < INC_) {
#pragma unroll
            for (int it = 0; it < 2; it++) {
                int i = tid + it * 256;
                int rr = i >> 4, cc = i & 15;
                pa[it] = *(const float4*)(g_wtc + (size_t)(k0 + 32 + rr) * MF_ + m0 + cc * 4);
                pb[it] = *(const float4*)(Xn + (size_t)(k0 + 32 + rr) * HW_ + p0 + cc * 4);
            }
        }
#pragma unroll
        for (int kk = 0; kk < 32; kk++) {
            float4 a = *(const float4*)&As[kk][tr * 4];
            ulonglong2 b2 = *(const ulonglong2*)&Bs[kk][tc * 4];
            unsigned long long a0 = pack2(a.x), a1 = pack2(a.y);
            unsigned long long a2 = pack2(a.z), a3 = pack2(a.w);
            acc[0][0] = fma2(a0, b2.x, acc[0][0]); acc[0][1] = fma2(a0, b2.y, acc[0][1]);
            acc[1][0] = fma2(a1, b2.x, acc[1][0]); acc[1][1] = fma2(a1, b2.y, acc[1][1]);
            acc[2][0] = fma2(a2, b2.x, acc[2][0]); acc[2][1] = fma2(a2, b2.y, acc[2][1]);
            acc[3][0] = fma2(a3, b2.x, acc[3][0]); acc[3][1] = fma2(a3, b2.y, acc[3][1]);
        }
    }

    int down = (m0 < CM_);
    float* Yn = down ? (g_t1 + ((size_t)n * CM_ + m0) * HW_ + p0)
                     : (g_y  + ((size_t)n * OUTC_ + (m0 - CM_)) * HW_ + p0);
#pragma unroll
    for (int i = 0; i < 4; i++) {
        float bi = down ? bDown[m0 + tr * 4 + i] : 0.f;
        float2 lo = unpack2(acc[i][0]);
        float2 hi = unpack2(acc[i][1]);
        float4 r;
        r.x = lo.x + bi; r.y = lo.y + bi;
        r.z = hi.x + bi; r.w = hi.y + bi;
        *(float4*)(Yn + (size_t)(tr * 4 + i) * HW_ + tc * 4) = r;
    }
}

// ---------------- K2a: enc 3x3 conv partials (round-4 proven version) ------
// grid: (32 tiles of 8x16 px, 4 ic-chunks, 4 n); block 256 = 8 warps.
__global__ void __launch_bounds__(256, 3) enc_part_kernel() {
    __shared__ float patch[8][10][40];
    __shared__ __align__(16) float ws[8][9][112];

    int n     = blockIdx.z;
    int chunk = blockIdx.y;
    int bx    = blockIdx.x;
    int h0 = (bx >> 2) * 8;
    int w0 = (bx & 3) * 16;
    int tid  = threadIdx.x;
    int wi   = tid >> 5, lane = tid & 31;
    int d    = wi >> 1;
    int pxg  = (wi & 1) * 32 + lane;
    int pr   = pxg >> 3, pc = pxg & 7;

    unsigned long long acc[2][12];
    float acc24[2];
#pragma unroll
    for (int p = 0; p < 2; p++) {
        acc24[p] = 0.f;
#pragma unroll
        for (int m = 0; m < 12; m++) acc[p][m] = 0ull;
    }

    for (int sc = 0; sc < 2; sc++) {
        int icbase = chunk * 16 + sc * 8;
        __syncthreads();
        for (int idx = tid; idx < 1440; idx += 256) {
            int ic = idx / 180, rem = idx % 180;
            int r = rem / 18, c = rem % 18;
            int gh = h0 - 1 + r, gw = w0 - 1 + c;
            float v = 0.f;
            if (gh >= 0 && gh < H_ && gw >= 0 && gw < W_)
                v = g_t1[(((size_t)n * CM_ + icbase + ic) * H_ + gh) * W_ + gw];
            patch[ic][r][c] = v;
        }
        {
            const float* src = g_wt + (size_t)icbase * 9 * 112;
            float* dst = &ws[0][0][0];
            for (int idx = tid; idx < 8 * 9 * 112; idx += 256) dst[idx] = src[idx];
        }
        __syncthreads();

#pragma unroll 2
        for (int ici = 0; ici < 8; ici++) {
#pragma unroll
            for (int t = 0; t < 9; t++) {
                int r = t / 3, c = t % 3;
                float va = patch[ici][pr + r][pc + c];
                float vb = patch[ici][pr + r][pc + 8 + c];
                unsigned long long va2 = pack2(va);
                unsigned long long vb2 = pack2(vb);
                const ulonglong2* wp = (const ulonglong2*)&ws[ici][t][d * 28];
#pragma unroll
                for (int q = 0; q < 6; q++) {
                    ulonglong2 w2 = wp[q];
                    acc[0][2 * q + 0] = fma2(w2.x, va2, acc[0][2 * q + 0]);
                    acc[0][2 * q + 1] = fma2(w2.y, va2, acc[0][2 * q + 1]);
                    acc[1][2 * q + 0] = fma2(w2.x, vb2, acc[1][2 * q + 0]);
                    acc[1][2 * q + 1] = fma2(w2.y, vb2, acc[1][2 * q + 1]);
                }
                float w24 = ws[ici][t][d * 28 + 24];
                acc24[0] += w24 * va;
                acc24[1] += w24 * vb;
            }
        }
    }

#pragma unroll
    for (int p = 0; p < 2; p++) {
        int hw = (h0 + pr) * W_ + w0 + pc + p * 8;
        float* o = g_part + ((size_t)(chunk * N_ + n) * 100 + d * 25) * HW_ + hw;
#pragma unroll
        for (int m = 0; m < 12; m++) {
            float2 v = unpack2(acc[p][m]);
            o[(size_t)(2 * m) * HW_]     = v.x;
            o[(size_t)(2 * m + 1) * HW_] = v.y;
        }
        o[(size_t)24 * HW_] = acc24[p];
    }
}

// ---------------- K2b: sum partials + bias + softmax over 25 k -------------
// grid 512 x 128 threads: thread = (px, d), 32 px per block
__global__ void softmax_kernel(const float* __restrict__ bEnc) {
    int tid = threadIdx.x;
    int d = tid >> 5;
    int p = blockIdx.x * 32 + (tid & 31);
    int n = p >> 12, hw = p & 4095;

    float v[25];
#pragma unroll
    for (int k = 0; k < 25; k++) {
        float s = bEnc[k * 4 + d];
        size_t base = ((size_t)n * 100 + d * 25 + k) * HW_ + hw;
#pragma unroll
        for (int c = 0; c < NCHUNK_; c++)
            s += g_part[(size_t)c * N_ * 100 * HW_ + base];
        v[k] = s;
    }

    float mx = v[0];
#pragma unroll
    for (int k = 1; k < 25; k++) mx = fmaxf(mx, v[k]);
    float s = 0.f;
#pragma unroll
    for (int k = 0; k < 25; k++) {
        float e = __expf(v[k] - mx);
        v[k] = e;
        s += e;
    }
    float inv = 1.f / s;

    float* o = g_kern + ((size_t)n * 100 + d * 25) * HW_ + hw;
#pragma unroll
    for (int k = 0; k < 25; k++) o[(size_t)k * HW_] = v[k] * inv;
}

// ---------------- K4: reassembly + pixel shuffle + bias (round-4 version) --
__global__ void __launch_bounds__(256) carafe_out_kernel(
        const float* __restrict__ bOut, float* __restrict__ out) {
    __shared__ float yp[144][36];
    __shared__ __align__(16) float ks[64 * 100];

    int n  = blockIdx.z;
    int o0 = blockIdx.y * 32;
    int bx = blockIdx.x;
    int h0 = (bx >> 3) * 8, w0 = (bx & 7) * 8;
    int tid = threadIdx.x;

    for (int idx = tid; idx < 32 * 144; idx += 256) {
        int o = idx / 144, pos = idx % 144;
        int yy = pos / 12, xx = pos % 12;
        int gh = h0 - 2 + yy, gw = w0 - 2 + xx;
        float v = 0.f;
        if (gh >= 0 && gh < H_ && gw >= 0 && gw < W_)
            v = g_y[(((size_t)n * OUTC_ + o0 + o) * H_ + gh) * W_ + gw];
        yp[pos][o] = v;
    }
    for (int idx = tid; idx < 6400; idx += 256) {
        int r = idx >> 6;
        int px = idx & 63;
        int dd = r / 25, k = r % 25;
        int h = h0 + (px >> 3), w = w0 + (px & 7);
        ks[px * 100 + k * 4 + dd] =
            g_kern[((size_t)n * 100 + r) * HW_ + h * W_ + w];
    }
    __syncthreads();

    int px = tid >> 2, oq = tid & 3;
    int pr = px >> 3, pc = px & 7;

    unsigned long long acc[8][2];
#pragma unroll
    for (int i = 0; i < 8; i++) { acc[i][0] = 0ull; acc[i][1] = 0ull; }

    for (int kh = 0; kh < 5; kh++) {
#pragma unroll
        for (int kw = 0; kw < 5; kw++) {
            ulonglong2 kv2 = *(const ulonglong2*)&ks[px * 100 + (kh * 5 + kw) * 4];
            const float* yr = &yp[(pr + kh) * 12 + pc + kw][oq];
#pragma unroll
            for (int i = 0; i < 8; i++) {
                unsigned long long yv2 = pack2(yr[i * 4]);
                acc[i][0] = fma2(kv2.x, yv2, acc[i][0]);
                acc[i][1] = fma2(kv2.y, yv2, acc[i][1]);
            }
        }
    }

    int oy = 2 * (h0 + pr);
    int ox = 2 * (w0 + pc);
#pragma unroll
    for (int i = 0; i < 8; i++) {
        int o = o0 + oq + 4 * i;
        float b = bOut[o];
        float* p = out + (((size_t)n * OUTC_ + o) * HO_ + oy) * HO_ + ox;
        float2 r0 = unpack2(acc[i][0]);
        float2 r1 = unpack2(acc[i][1]);
        r0.x += b; r0.y += b; r1.x += b; r1.y += b;
        *(float2*)p = r0;
        *(float2*)(p + HO_) = r1;
    }
}

// ---------------- launch ----------------------------------------------------
extern "C" void kernel_launch(void* const* d_in, const int* in_sizes, int n_in,
                              void* d_out, int out_size) {
    (void)in_sizes; (void)n_in; (void)out_size;
    const float* x      = (const float*)d_in[0];
    const float* w_down = (const float*)d_in[1];
    const float* b_down = (const float*)d_in[2];
    const float* w_enc  = (const float*)d_in[3];
    const float* b_enc  = (const float*)d_in[4];
    const float* w_out  = (const float*)d_in[5];
    const float* b_out  = (const float*)d_in[6];
    float* out = (float*)d_out;

    // K0: weight transposes (enc + fused conv weights)
    wt_kernel<<<572, 256>>>(w_enc, w_out, w_down);
    // K1+K3 fused: both 1x1 convs in one launch -> g_t1, g_y
    convfused_kernel<<<dim3(5, 64, 4), 256>>>(x, b_down);
    // K2a: enc 3x3 conv partials -> g_part
    enc_part_kernel<<<dim3(32, NCHUNK_, 4), 256>>>();
    // K2b: sum + softmax -> g_kern (channel-major)
    softmax_kernel<<<512, 128>>>(b_enc);
    // K4: reassembly + pixel shuffle + bias -> out
    carafe_out_kernel<<<dim3(64, 8, 4), 256>>>(b_out, out);
}